// round 1
// baseline (speedup 1.0000x reference)
#include <cuda_runtime.h>
#include <math.h>
#include <stdint.h>

#define Bn    16
#define Cin   128
#define Hh    32
#define Ww    32
#define HW    1024
#define MID   512
#define OUTC  111
#define NE    4
#define BOUT  (Bn*OUTC)   // 1776

// ---------------- scratch (device globals; no allocations allowed) ----------
__device__ float g_routing[Bn*NE];                        // [B][E]
__device__ float g_comb[(size_t)Bn*Cin*MID*49];           // [B][ic][o][49]  ~205MB
__device__ float g_y[(size_t)Bn*MID*HW];                  // raw conv output ~33.5MB
__device__ float g_ymean[Bn*MID];
__device__ float g_ca[Bn*MID];
__device__ float g_mf[Bn*HW];

// ---------------- init: zero count region + ymean ---------------------------
__global__ void init_kernel(float* out) {
    int i = blockIdx.x*256 + threadIdx.x;
    if (i < BOUT)    out[i] = 0.f;
    if (i < Bn*MID)  g_ymean[i] = 0.f;
}

// ---------------- routing: pooled mean -> softmax ---------------------------
__global__ void routing_kernel(const float* __restrict__ x,
                               const float* __restrict__ rw,
                               const float* __restrict__ rb) {
    int b = blockIdx.x;
    __shared__ float pooled[Cin];
    __shared__ float logit[NE];
    int t = threadIdx.x, warp = t >> 5, lane = t & 31;
    const float* xb = x + (size_t)b*Cin*HW;
    for (int c = warp; c < Cin; c += 8) {
        float s = 0.f;
        for (int i = lane; i < HW; i += 32) s += xb[c*HW + i];
        #pragma unroll
        for (int off = 16; off; off >>= 1) s += __shfl_down_sync(0xffffffffu, s, off);
        if (lane == 0) pooled[c] = s * (1.0f/HW);
    }
    __syncthreads();
    if (t < NE) {
        float s = rb[t];
        for (int c = 0; c < Cin; c++) s += pooled[c] * rw[t*Cin + c];
        logit[t] = s;
    }
    __syncthreads();
    if (t == 0) {
        float m = fmaxf(fmaxf(logit[0],logit[1]), fmaxf(logit[2],logit[3]));
        float e[NE]; float sum = 0.f;
        #pragma unroll
        for (int e_i = 0; e_i < NE; e_i++) { e[e_i] = expf(logit[e_i]-m); sum += e[e_i]; }
        float inv = 1.f/sum;
        #pragma unroll
        for (int e_i = 0; e_i < NE; e_i++) g_routing[b*NE + e_i] = e[e_i]*inv;
    }
}

// ---------------- combine experts into per-sample merged 7x7 bank ------------
// g_comb[b][ic][o][t7] = sum_e r[b,e]*(w7 + embed(w5) + embed(w3))
__global__ void combine_kernel(const float* __restrict__ w3,
                               const float* __restrict__ w5,
                               const float* __restrict__ w7) {
    __shared__ float r[Bn*NE];
    if (threadIdx.x < Bn*NE) r[threadIdx.x] = g_routing[threadIdx.x];
    __syncthreads();
    int idx = blockIdx.x*blockDim.x + threadIdx.x;
    const int TOT = MID*Cin*49;
    if (idx >= TOT) return;
    int o   = idx / (Cin*49);
    int rem = idx % (Cin*49);
    int ic  = rem / 49;
    int t   = rem % 49;
    int ty = t / 7, tx = t % 7;
    float v[NE];
    #pragma unroll
    for (int e = 0; e < NE; e++) {
        float w = w7[(((size_t)e*MID + o)*Cin + ic)*49 + t];
        if (ty >= 1 && ty <= 5 && tx >= 1 && tx <= 5)
            w += w5[(((size_t)e*MID + o)*Cin + ic)*25 + (ty-1)*5 + (tx-1)];
        if (ty >= 2 && ty <= 4 && tx >= 2 && tx <= 4)
            w += w3[(((size_t)e*MID + o)*Cin + ic)*9  + (ty-2)*3 + (tx-2)];
        v[e] = w;
    }
    #pragma unroll
    for (int b = 0; b < Bn; b++) {
        float s = r[b*NE+0]*v[0] + r[b*NE+1]*v[1] + r[b*NE+2]*v[2] + r[b*NE+3]*v[3];
        g_comb[(((size_t)b*Cin + ic)*MID + o)*49 + t] = s;
    }
}

// ---------------- main conv: per-sample 7x7, 512x(32x32), K=128 --------------
// grid (4 h-tiles, 8 o-tiles, 16 b); block 256.
// thread: col = t&31, og = t>>5; computes o = o0+og*8+k (k<8), rows h0+r (r<8), col.
__global__ void __launch_bounds__(256, 2)
conv_kernel(const float* __restrict__ x) {
    int b = blockIdx.z, ot = blockIdx.y, ht = blockIdx.x;
    int h0 = ht*8, o0 = ot*64;
    int tid = threadIdx.x;
    int col = tid & 31, og = tid >> 5;

    __shared__ float xs[8][14*38];     // 8 ic, 14 rows halo, 38 cols halo
    __shared__ float ws[2][64*49];     // [icl][o_local*49 + tap]

    float acc[8][8];
    #pragma unroll
    for (int k = 0; k < 8; k++)
        #pragma unroll
        for (int r = 0; r < 8; r++) acc[k][r] = 0.f;

    const float* xb = x + (size_t)b*Cin*HW;

    for (int ic0 = 0; ic0 < Cin; ic0 += 8) {
        __syncthreads();
        // stage input tile with halo (zero-padded)
        for (int i = tid; i < 8*532; i += 256) {
            int icl = i / 532, j = i % 532;
            int ri = j / 38, ci = j % 38;
            int hh = h0 - 3 + ri, wc = ci - 3;
            float v = 0.f;
            if ((unsigned)hh < 32u && (unsigned)wc < 32u)
                v = xb[(ic0+icl)*HW + hh*32 + wc];
            xs[icl][j] = v;
        }
        const float* combB = g_comb + (((size_t)b*Cin + ic0)*MID + o0)*49;
        for (int icp = 0; icp < 8; icp += 2) {
            __syncthreads();
            // stage weights for two input channels (coalesced global, conflict-free smem)
            for (int i = tid; i < 2*64*49; i += 256) {
                int l = i / 3136, j = i % 3136;   // j = ol*49 + t (matches global layout)
                ws[l][j] = combB[((size_t)(icp+l)*MID)*49 + j];
            }
            __syncthreads();
            #pragma unroll
            for (int l = 0; l < 2; l++) {
                const float* xsl = xs[icp + l];
                const float* wsl = ws[l] + og*8*49;
                #pragma unroll 1
                for (int ky = 0; ky < 7; ky++) {
                    #pragma unroll
                    for (int kx = 0; kx < 7; kx++) {
                        int t7 = ky*7 + kx;
                        float w[8];
                        #pragma unroll
                        for (int k = 0; k < 8; k++) w[k] = wsl[k*49 + t7];
                        float xv[8];
                        #pragma unroll
                        for (int r = 0; r < 8; r++)
                            xv[r] = xsl[(r+ky)*38 + col + kx];
                        #pragma unroll
                        for (int r = 0; r < 8; r++) {
                            #pragma unroll
                            for (int k = 0; k < 8; k++)
                                acc[k][r] += w[k] * xv[r];
                        }
                    }
                }
            }
        }
    }

    // write y + accumulate spatial means (for channel attention)
    #pragma unroll
    for (int k = 0; k < 8; k++) {
        int o = o0 + og*8 + k;
        float s = 0.f;
        float* yb = g_y + ((size_t)b*MID + o)*HW + h0*32 + col;
        #pragma unroll
        for (int r = 0; r < 8; r++) { yb[r*32] = acc[k][r]; s += acc[k][r]; }
        #pragma unroll
        for (int off = 16; off; off >>= 1) s += __shfl_down_sync(0xffffffffu, s, off);
        if (col == 0) atomicAdd(&g_ymean[b*MID + o], s);
    }
}

// ---------------- channel attention MLP -------------------------------------
__global__ void ca_kernel(const float* __restrict__ fc1w, const float* __restrict__ fc1b,
                          const float* __restrict__ fc2w, const float* __restrict__ fc2b) {
    int b = blockIdx.x, t = threadIdx.x;   // 512 threads
    __shared__ float m[MID];
    __shared__ float h[32];
    m[t] = g_ymean[b*MID + t] * (1.0f/HW);
    __syncthreads();
    if (t < 32) {
        float s = fc1b[t];
        for (int c = 0; c < MID; c++) s += fc1w[t*MID + c] * m[c];
        h[t] = fmaxf(s, 0.f);
    }
    __syncthreads();
    float s = fc2b[t];
    #pragma unroll
    for (int j = 0; j < 32; j++) s += fc2w[t*32 + j] * h[j];
    g_ca[b*MID + t] = 1.f/(1.f + expf(-s));
}

// ---------------- mask projection (1x1, 128 -> 1) ----------------------------
__global__ void mf_kernel(const float* __restrict__ mask,
                          const float* __restrict__ mpw,
                          const float* __restrict__ mpb) {
    __shared__ float w[Cin];
    int t = threadIdx.x;
    if (t < Cin) w[t] = mpw[t];
    __syncthreads();
    int b = blockIdx.y;
    int p = blockIdx.x*256 + t;
    const float* mb = mask + (size_t)b*Cin*HW + p;
    float s = mpb[0];
    #pragma unroll 8
    for (int c = 0; c < Cin; c++) s += mb[c*HW] * w[c];
    g_mf[b*HW + p] = s;
}

// ---------------- final: per-sample pred GEMM + sigmoid + count --------------
// grid (16 b, 8 p-tiles); block 128 (one spatial position each).
// ca folds into pred weights; mask_feat multiplies logits.
__global__ void __launch_bounds__(128)
final_kernel(const float* __restrict__ predw, float* __restrict__ out) {
    int b = blockIdx.x, pt = blockIdx.y;
    int t = threadIdx.x;
    int p = pt*128 + t;

    __shared__ float pw[64][112];
    float4 acc[28];
    #pragma unroll
    for (int j = 0; j < 28; j++) acc[j] = make_float4(0.f,0.f,0.f,0.f);

    for (int c0 = 0; c0 < MID; c0 += 64) {
        __syncthreads();
        for (int i = t; i < 64*112; i += 128) {
            int cl = i / 112, o = i % 112;
            float v = 0.f;
            if (o < OUTC) v = predw[o*MID + c0 + cl] * g_ca[b*MID + c0 + cl];
            pw[cl][o] = v;
        }
        __syncthreads();
        const float* yb = g_y + ((size_t)b*MID + c0)*HW + p;
        #pragma unroll 4
        for (int cl = 0; cl < 64; cl++) {
            float yv = yb[(size_t)cl*HW];
            const float4* pw4 = (const float4*)pw[cl];
            #pragma unroll
            for (int j = 0; j < 28; j++) {
                float4 w4 = pw4[j];
                acc[j].x += w4.x*yv; acc[j].y += w4.y*yv;
                acc[j].z += w4.z*yv; acc[j].w += w4.w*yv;
            }
        }
    }

    float mf = g_mf[b*HW + p];
    float* dbase = out + BOUT + ((size_t)b*OUTC)*HW + p;
    float* cnt   = out + b*OUTC;
    int lane = t & 31;

#define EMIT(OO, AV) do {                                              \
        if ((OO) < OUTC) {                                             \
            float dv = 1.f/(1.f + expf(-(AV)*mf));                     \
            dbase[(size_t)(OO)*HW] = dv;                               \
            float s_ = dv;                                             \
            s_ += __shfl_down_sync(0xffffffffu, s_, 16);               \
            s_ += __shfl_down_sync(0xffffffffu, s_, 8);                \
            s_ += __shfl_down_sync(0xffffffffu, s_, 4);                \
            s_ += __shfl_down_sync(0xffffffffu, s_, 2);                \
            s_ += __shfl_down_sync(0xffffffffu, s_, 1);                \
            if (lane == 0) atomicAdd(&cnt[(OO)], s_);                  \
        }                                                              \
    } while (0)

    #pragma unroll
    for (int j = 0; j < 28; j++) {
        float4 a = acc[j];
        EMIT(4*j+0, a.x); EMIT(4*j+1, a.y);
        EMIT(4*j+2, a.z); EMIT(4*j+3, a.w);
    }
#undef EMIT
}

// ---------------- launch ------------------------------------------------------
extern "C" void kernel_launch(void* const* d_in, const int* in_sizes, int n_in,
                              void* d_out, int out_size) {
    const float* x        = (const float*)d_in[0];
    const float* mask     = (const float*)d_in[1];
    const float* w3       = (const float*)d_in[2];
    const float* w5       = (const float*)d_in[3];
    const float* w7       = (const float*)d_in[4];
    const float* router_w = (const float*)d_in[5];
    const float* router_b = (const float*)d_in[6];
    const float* fc1_w    = (const float*)d_in[7];
    const float* fc1_b    = (const float*)d_in[8];
    const float* fc2_w    = (const float*)d_in[9];
    const float* fc2_b    = (const float*)d_in[10];
    const float* mpw      = (const float*)d_in[11];
    const float* mpb      = (const float*)d_in[12];
    const float* pred_w   = (const float*)d_in[13];
    float* out = (float*)d_out;

    init_kernel<<<32, 256>>>(out);
    routing_kernel<<<Bn, 256>>>(x, router_w, router_b);
    {
        const int TOT = MID*Cin*49;
        combine_kernel<<<(TOT + 255)/256, 256>>>(w3, w5, w7);
    }
    conv_kernel<<<dim3(4, 8, Bn), 256>>>(x);
    mf_kernel<<<dim3(4, Bn), 256>>>(mask, mpw, mpb);
    ca_kernel<<<Bn, 512>>>(fc1_w, fc1_b, fc2_w, fc2_b);
    final_kernel<<<dim3(Bn, 8), 128>>>(pred_w, out);
}